// round 10
// baseline (speedup 1.0000x reference)
#include <cuda_runtime.h>
#include <math.h>

#define B_  256
#define T_  512
#define I_  256
#define H_  512
#define G3  1536   // 3*H
#define NBLK 128

// ---------------- scratch (device globals: no allocation allowed) ----------
__device__ __align__(16) float g_igates[(size_t)T_ * B_ * G3]; // (t,b,g)
__device__ __align__(16) float g_h2[2][B_ * H_];               // double-buffered h
__device__ unsigned g_bar;                                     // global barrier ctr

// ---------------- packed fp32x2 FMA (sm_100a+/103a) ------------------------
__device__ __forceinline__ unsigned long long ffma2(unsigned long long a,
                                                    unsigned long long b,
                                                    unsigned long long c) {
    unsigned long long d;
    asm("fma.rn.f32x2 %0, %1, %2, %3;" : "=l"(d) : "l"(a), "l"(b), "l"(c));
    return d;
}
__device__ __forceinline__ float pairsum(unsigned long long v) {
    float lo = __uint_as_float((unsigned int)(v & 0xffffffffull));
    float hi = __uint_as_float((unsigned int)(v >> 32));
    return lo + hi;
}
// 16B global load -> two 8B SMEM stores (row strides are 8B- but not 16B-
// aligned; STS.128 would trap "misaligned address").
__device__ __forceinline__ void stage16(float* dst, const float* src) {
    float4 v = *(const float4*)src;
    *(float2*)(dst + 0) = make_float2(v.x, v.y);
    *(float2*)(dst + 2) = make_float2(v.z, v.w);
}
__device__ __forceinline__ void sts16(float* dst, float4 v) {
    *(float2*)(dst + 0) = make_float2(v.x, v.y);
    *(float2*)(dst + 2) = make_float2(v.z, v.w);
}

// ======================= Kernel 1: igates GEMM ==============================
// igates[t][b][g] = sum_i x[b][t][i] * w_ih[g][i] + bias[g]
__global__ __launch_bounds__(256) void igates_kernel(
        const float* __restrict__ x, const float* __restrict__ w_ih,
        const float* __restrict__ bias) {
    __shared__ __align__(16) float xs[64][70];  // stride 70 == 6 mod 32
    __shared__ __align__(16) float ws[64][70];

    const int tid = threadIdx.x;
    const int tx = tid & 15;
    const int ty = tid >> 4;
    const int n0 = blockIdx.x * 64;
    const int m0 = blockIdx.y * 64;

    unsigned long long acc[4][4];
#pragma unroll
    for (int i = 0; i < 4; i++)
#pragma unroll
        for (int j = 0; j < 4; j++) acc[i][j] = 0ull;

    for (int kc = 0; kc < 4; kc++) {
        const int kb = kc * 64;
#pragma unroll
        for (int q = 0; q < 4; q++) {
            int qi = tid + 256 * q;
            int r = qi >> 4, kq = qi & 15;
            stage16(&xs[r][kq * 4], &x[(size_t)(m0 + r) * I_ + kb + kq * 4]);
            stage16(&ws[r][kq * 4], &w_ih[(size_t)(n0 + r) * I_ + kb + kq * 4]);
        }
        __syncthreads();
#pragma unroll 4
        for (int k2 = 0; k2 < 32; k2++) {
            unsigned long long xv[4], wv[4];
#pragma unroll
            for (int i = 0; i < 4; i++)
                xv[i] = *(const unsigned long long*)&xs[ty + 16 * i][2 * k2];
#pragma unroll
            for (int j = 0; j < 4; j++)
                wv[j] = *(const unsigned long long*)&ws[tx + 16 * j][2 * k2];
#pragma unroll
            for (int i = 0; i < 4; i++)
#pragma unroll
                for (int j = 0; j < 4; j++)
                    acc[i][j] = ffma2(xv[i], wv[j], acc[i][j]);
        }
        __syncthreads();
    }
#pragma unroll
    for (int i = 0; i < 4; i++) {
        int m = m0 + ty + 16 * i;
        int t = m & (T_ - 1);
        int bb = m >> 9;
        size_t base = ((size_t)t * B_ + bb) * G3;
#pragma unroll
        for (int j = 0; j < 4; j++) {
            int n = n0 + tx + 16 * j;
            g_igates[base + n] = pairsum(acc[i][j]) + bias[n];
        }
    }
}

// ============== Kernel 2: persistent GRU recurrence (512 steps) =============
// 128 blocks x 256 threads, one block/SM (217KB SMEM), all co-resident.
// w_hh tile (96 rows x 512 K) is loaded into SMEM ONCE and stays resident;
// per step only the 32x512 h tile streams through double-buffered SMEM chunks.
#define WS_STRIDE 518                 // == 6 mod 32 floats, 8B-aligned rows
#define HS_STRIDE 70
#define WS_FLOATS (96 * WS_STRIDE)    // 49728
#define HS_FLOATS (32 * HS_STRIDE)    // 2240
#define SMEM_BYTES ((WS_FLOATS + 2 * HS_FLOATS) * 4)   // 216832 B

__global__ __launch_bounds__(256) void recur_kernel(
        const float* __restrict__ w_hh, const float* __restrict__ b_n) {
    extern __shared__ float smem[];
    float* ws = smem;                          // [96][WS_STRIDE]
    float* hs = smem + WS_FLOATS;              // [2][32][HS_STRIDE]

    const int tid = threadIdx.x;
    const int tx = tid & 15;                   // j-sub
    const int ty = (tid >> 4) & 7;             // b-group
    const int tz = tid >> 7;                   // j-half (0/1)
    const int j0 = (blockIdx.x & 15) * 32;
    const int b0 = (blockIdx.x >> 4) * 32;
    const int jj = tx + 16 * tz;               // 0..31 within tile
    const int jg = j0 + jj;                    // global j

    // ---- load stationary w tile: rows 0..95 = gate g rows j0..j0+31 --------
    for (int q = 0; q < 48; q++) {
        int qi = tid + 256 * q;                // [0, 12288) float4 ids
        int r = qi >> 7;                       // 0..95
        int c4 = qi & 127;                     // float4 col 0..127
        int grow = (r >> 5) * H_ + j0 + (r & 31);
        stage16(&ws[r * WS_STRIDE + c4 * 4],
                &w_hh[(size_t)grow * H_ + c4 * 4]);
    }

    float bnv = b_n[jg];
    __syncthreads();

    for (int t = 0; t < T_; t++) {
        const float* __restrict__ hprev = g_h2[t & 1];
        float* __restrict__ hnext = g_h2[(t + 1) & 1];

        // ---- prefetch pointwise operands (independent of the GEMM) --------
        float igv[3][4], hval[4];
#pragma unroll
        for (int i = 0; i < 4; i++) {
            int b = b0 + ty + 8 * i;
            size_t ib = ((size_t)t * B_ + b) * G3;
            igv[0][i] = g_igates[ib + jg];
            igv[1][i] = g_igates[ib + H_ + jg];
            igv[2][i] = g_igates[ib + 2 * H_ + jg];
            hval[i] = hprev[b * H_ + jg];
        }

        // ---- stage h chunk 0 ------------------------------------------------
#pragma unroll
        for (int q = 0; q < 2; q++) {
            int qi = tid + 256 * q;            // [0,512) float4 ids
            int r = qi >> 4, kq = qi & 15;
            stage16(&hs[r * HS_STRIDE + kq * 4],
                    &hprev[(size_t)(b0 + r) * H_ + kq * 4]);
        }
        __syncthreads();

        unsigned long long acc[4][3];
#pragma unroll
        for (int i = 0; i < 4; i++)
#pragma unroll
            for (int g = 0; g < 3; g++) acc[i][g] = 0ull;

        for (int kc = 0; kc < 8; kc++) {
            // prefetch next h chunk into registers (hidden behind compute)
            float4 nv0, nv1;
            int r0 = 0, c0 = 0, r1 = 0, c1 = 0;
            if (kc < 7) {
                int kb = (kc + 1) * 64;
                int qi = tid;
                r0 = qi >> 4; c0 = qi & 15;
                nv0 = *(const float4*)&hprev[(size_t)(b0 + r0) * H_ + kb + c0 * 4];
                qi = tid + 256;
                r1 = qi >> 4; c1 = qi & 15;
                nv1 = *(const float4*)&hprev[(size_t)(b0 + r1) * H_ + kb + c1 * 4];
            }

            const float* hb = hs + (kc & 1) * HS_FLOATS;
            const int wc = kc * 64;
#pragma unroll 4
            for (int k2 = 0; k2 < 32; k2++) {
                unsigned long long hv[4], wv[3];
#pragma unroll
                for (int i = 0; i < 4; i++)
                    hv[i] = *(const unsigned long long*)
                        &hb[(ty + 8 * i) * HS_STRIDE + 2 * k2];
#pragma unroll
                for (int g = 0; g < 3; g++)
                    wv[g] = *(const unsigned long long*)
                        &ws[(g * 32 + jj) * WS_STRIDE + wc + 2 * k2];
#pragma unroll
                for (int i = 0; i < 4; i++)
#pragma unroll
                    for (int g = 0; g < 3; g++)
                        acc[i][g] = ffma2(hv[i], wv[g], acc[i][g]);
            }
            if (kc < 7) {
                float* nb = hs + ((kc + 1) & 1) * HS_FLOATS;
                sts16(&nb[r0 * HS_STRIDE + c0 * 4], nv0);
                sts16(&nb[r1 * HS_STRIDE + c1 * 4], nv1);
            }
            __syncthreads();
        }

        // ---- GRU pointwise in registers ------------------------------------
#pragma unroll
        for (int i = 0; i < 4; i++) {
            int b = b0 + ty + 8 * i;
            float sr = pairsum(acc[i][0]);
            float sz = pairsum(acc[i][1]);
            float sn = pairsum(acc[i][2]);
            float r = 1.0f / (1.0f + expf(-(igv[0][i] + sr)));
            float z = 1.0f / (1.0f + expf(-(igv[1][i] + sz)));
            float n = tanhf(igv[2][i] + r * (sn + bnv));
            hnext[b * H_ + jg] = n + z * (hval[i] - n);
        }

        // ---- device-wide barrier (all 128 blocks resident) -----------------
        __threadfence();
        __syncthreads();
        if (tid == 0) {
            atomicAdd(&g_bar, 1u);
            unsigned target = (unsigned)(t + 1) * NBLK;
            volatile unsigned* p = &g_bar;
            while (*p < target) { }
        }
        __syncthreads();
    }
}

// ======================= Kernel 3: final projection =========================
__global__ __launch_bounds__(128) void proj_kernel(
        const float* __restrict__ w_proj, const float* __restrict__ b_proj,
        float* __restrict__ out) {
    __shared__ float red[4];
    int b = blockIdx.x;
    float s = 0.f;
    for (int j = threadIdx.x; j < H_; j += 128)
        s += g_h2[0][b * H_ + j] * w_proj[j];   // T=512 even -> final h in buf 0
#pragma unroll
    for (int o = 16; o; o >>= 1) s += __shfl_down_sync(0xffffffffu, s, o);
    if ((threadIdx.x & 31) == 0) red[threadIdx.x >> 5] = s;
    __syncthreads();
    if (threadIdx.x == 0)
        out[b] = red[0] + red[1] + red[2] + red[3] + b_proj[0];
}

__global__ void zero_kernel() {
    int i = blockIdx.x * 256 + threadIdx.x;
    if (i < B_ * H_) g_h2[0][i] = 0.f;
    if (i == 0) g_bar = 0u;     // reset barrier counter every launch/replay
}

// ======================= launch ============================================
extern "C" void kernel_launch(void* const* d_in, const int* in_sizes, int n_in,
                              void* d_out, int out_size) {
    const float* x      = (const float*)d_in[0];  // (B,T,I)
    const float* w_ih   = (const float*)d_in[1];  // (3H,I)
    const float* w_hh   = (const float*)d_in[2];  // (3H,H)
    const float* b      = (const float*)d_in[3];  // (3H)
    const float* b_n    = (const float*)d_in[4];  // (H)
    const float* w_proj = (const float*)d_in[5];  // (1,H)
    const float* b_proj = (const float*)d_in[6];  // (1)
    float* out = (float*)d_out;                   // (B)

    cudaFuncSetAttribute(recur_kernel,
                         cudaFuncAttributeMaxDynamicSharedMemorySize,
                         SMEM_BYTES);

    igates_kernel<<<dim3(G3 / 64, (B_ * T_) / 64), 256>>>(x, w_ih, b);
    zero_kernel<<<(B_ * H_) / 256, 256>>>();
    recur_kernel<<<NBLK, 256, SMEM_BYTES>>>(w_hh, b_n);
    proj_kernel<<<B_, 128>>>(w_proj, b_proj, out);
}

// round 11
// speedup vs baseline: 1.0410x; 1.0410x over previous
#include <cuda_runtime.h>
#include <math.h>

#define B_  256
#define T_  512
#define I_  256
#define H_  512
#define G3  1536   // 3*H
#define NBLK 128

// ---------------- scratch (device globals: no allocation allowed) ----------
__device__ __align__(16) float g_igates[(size_t)T_ * B_ * G3]; // (t,b,g)
__device__ __align__(16) float g_h2[2][B_ * H_];               // double-buffered h
__device__ __align__(128) unsigned g_bars[8 * 32];             // 8 group ctrs, 128B apart

// ---------------- packed fp32x2 FMA (sm_100a+/103a) ------------------------
__device__ __forceinline__ unsigned long long ffma2(unsigned long long a,
                                                    unsigned long long b,
                                                    unsigned long long c) {
    unsigned long long d;
    asm("fma.rn.f32x2 %0, %1, %2, %3;" : "=l"(d) : "l"(a), "l"(b), "l"(c));
    return d;
}
__device__ __forceinline__ float pairsum(unsigned long long v) {
    float lo = __uint_as_float((unsigned int)(v & 0xffffffffull));
    float hi = __uint_as_float((unsigned int)(v >> 32));
    return lo + hi;
}
// 16B global load -> two 8B SMEM stores (row strides are 8B- but not 16B-
// aligned; STS.128 would trap "misaligned address").
__device__ __forceinline__ void stage16(float* dst, const float* src) {
    float4 v = *(const float4*)src;
    *(float2*)(dst + 0) = make_float2(v.x, v.y);
    *(float2*)(dst + 2) = make_float2(v.z, v.w);
}
__device__ __forceinline__ void sts16(float* dst, float4 v) {
    *(float2*)(dst + 0) = make_float2(v.x, v.y);
    *(float2*)(dst + 2) = make_float2(v.z, v.w);
}

// ======================= Kernel 1: igates GEMM ==============================
__global__ __launch_bounds__(256) void igates_kernel(
        const float* __restrict__ x, const float* __restrict__ w_ih,
        const float* __restrict__ bias) {
    __shared__ __align__(16) float xs[64][70];  // stride 70 == 6 mod 32
    __shared__ __align__(16) float ws[64][70];

    const int tid = threadIdx.x;
    const int tx = tid & 15;
    const int ty = tid >> 4;
    const int n0 = blockIdx.x * 64;
    const int m0 = blockIdx.y * 64;

    unsigned long long acc[4][4];
#pragma unroll
    for (int i = 0; i < 4; i++)
#pragma unroll
        for (int j = 0; j < 4; j++) acc[i][j] = 0ull;

    for (int kc = 0; kc < 4; kc++) {
        const int kb = kc * 64;
#pragma unroll
        for (int q = 0; q < 4; q++) {
            int qi = tid + 256 * q;
            int r = qi >> 4, kq = qi & 15;
            stage16(&xs[r][kq * 4], &x[(size_t)(m0 + r) * I_ + kb + kq * 4]);
            stage16(&ws[r][kq * 4], &w_ih[(size_t)(n0 + r) * I_ + kb + kq * 4]);
        }
        __syncthreads();
#pragma unroll 4
        for (int k2 = 0; k2 < 32; k2++) {
            unsigned long long xv[4], wv[4];
#pragma unroll
            for (int i = 0; i < 4; i++)
                xv[i] = *(const unsigned long long*)&xs[ty + 16 * i][2 * k2];
#pragma unroll
            for (int j = 0; j < 4; j++)
                wv[j] = *(const unsigned long long*)&ws[tx + 16 * j][2 * k2];
#pragma unroll
            for (int i = 0; i < 4; i++)
#pragma unroll
                for (int j = 0; j < 4; j++)
                    acc[i][j] = ffma2(xv[i], wv[j], acc[i][j]);
        }
        __syncthreads();
    }
#pragma unroll
    for (int i = 0; i < 4; i++) {
        int m = m0 + ty + 16 * i;
        int t = m & (T_ - 1);
        int bb = m >> 9;
        size_t base = ((size_t)t * B_ + bb) * G3;
#pragma unroll
        for (int j = 0; j < 4; j++) {
            int n = n0 + tx + 16 * j;
            g_igates[base + n] = pairsum(acc[i][j]) + bias[n];
        }
    }
}

// ============== Kernel 2: persistent GRU recurrence (512 steps) =============
// 128 blocks x 512 threads (4 warps/SMSP), 1 block/SM (217KB SMEM).
// w_hh tile (96 x 512) stationary in SMEM; h tile streams through double-
// buffered chunks. Barrier is PER b-GROUP (16 blocks), not device-wide.
#define WS_STRIDE 518                 // == 6 mod 32 floats, 8B-aligned rows
#define HS_STRIDE 70
#define WS_FLOATS (96 * WS_STRIDE)    // 49728
#define HS_FLOATS (32 * HS_STRIDE)    // 2240
#define SMEM_BYTES ((WS_FLOATS + 2 * HS_FLOATS) * 4)   // 216832 B

__global__ __launch_bounds__(512) void recur_kernel(
        const float* __restrict__ w_hh, const float* __restrict__ b_n) {
    extern __shared__ float smem[];
    float* ws = smem;                          // [96][WS_STRIDE]
    float* hs = smem + WS_FLOATS;              // [2][32][HS_STRIDE]

    const int tid = threadIdx.x;
    const int tx = tid & 15;                   // j-sub (fast: keeps GMEM coalesced)
    const int ty = (tid >> 4) & 15;            // b-sub (0..15)
    const int tz = tid >> 8;                   // j-half
    const int j0 = (blockIdx.x & 15) * 32;
    const int b0 = (blockIdx.x >> 4) * 32;
    const int grp = blockIdx.x >> 4;           // b-group id (0..7)
    const int jj = tx + 16 * tz;               // 0..31 within tile
    const int jg = j0 + jj;

    // ---- stationary w tile: rows 0..95 = gate g, j0..j0+31 -----------------
    for (int q = 0; q < 24; q++) {
        int qi = tid + 512 * q;                // [0, 12288) float4 ids
        int r = qi >> 7;                       // 0..95
        int c4 = qi & 127;
        int grow = (r >> 5) * H_ + j0 + (r & 31);
        stage16(&ws[r * WS_STRIDE + c4 * 4], &w_hh[(size_t)grow * H_ + c4 * 4]);
    }
    float bnv = b_n[jg];

    const int hr = tid >> 4;                   // 0..31 (staging row)
    const int hc = tid & 15;                   // staging float4 col
    __syncthreads();

    for (int t = 0; t < T_; t++) {
        const float* __restrict__ hprev = g_h2[t & 1];
        float* __restrict__ hnext = g_h2[(t + 1) & 1];

        // ---- prefetch pointwise operands (coalesced: tx fast over jg) ------
        float igv[3][2], hval[2];
#pragma unroll
        for (int i = 0; i < 2; i++) {
            int b = b0 + ty + 16 * i;
            size_t ib = ((size_t)t * B_ + b) * G3;
            igv[0][i] = g_igates[ib + jg];
            igv[1][i] = g_igates[ib + H_ + jg];
            igv[2][i] = g_igates[ib + 2 * H_ + jg];
            hval[i] = __ldcg(&hprev[b * H_ + jg]);   // L2: other-SM producer
        }

        // ---- stage h chunk 0 (one float4 per thread) -----------------------
        {
            float4 v = __ldcg((const float4*)&hprev[(size_t)(b0 + hr) * H_ + hc * 4]);
            sts16(&hs[hr * HS_STRIDE + hc * 4], v);
        }
        __syncthreads();

        unsigned long long acc[2][3];
#pragma unroll
        for (int i = 0; i < 2; i++)
#pragma unroll
            for (int g = 0; g < 3; g++) acc[i][g] = 0ull;

        for (int kc = 0; kc < 8; kc++) {
            float4 nv;
            if (kc < 7)
                nv = __ldcg((const float4*)
                        &hprev[(size_t)(b0 + hr) * H_ + (kc + 1) * 64 + hc * 4]);

            const float* hb = hs + (kc & 1) * HS_FLOATS;
            const int wc = kc * 64;
#pragma unroll 4
            for (int k2 = 0; k2 < 32; k2++) {
                unsigned long long hv[2], wv[3];
#pragma unroll
                for (int i = 0; i < 2; i++)
                    hv[i] = *(const unsigned long long*)
                        &hb[(ty + 16 * i) * HS_STRIDE + 2 * k2];
#pragma unroll
                for (int g = 0; g < 3; g++)
                    wv[g] = *(const unsigned long long*)
                        &ws[(g * 32 + jj) * WS_STRIDE + wc + 2 * k2];
#pragma unroll
                for (int i = 0; i < 2; i++)
#pragma unroll
                    for (int g = 0; g < 3; g++)
                        acc[i][g] = ffma2(hv[i], wv[g], acc[i][g]);
            }
            if (kc < 7)
                sts16(&hs[((kc + 1) & 1) * HS_FLOATS + hr * HS_STRIDE + hc * 4], nv);
            __syncthreads();
        }

        // ---- GRU pointwise in registers ------------------------------------
#pragma unroll
        for (int i = 0; i < 2; i++) {
            int b = b0 + ty + 16 * i;
            float sr = pairsum(acc[i][0]);
            float sz = pairsum(acc[i][1]);
            float sn = pairsum(acc[i][2]);
            float r = 1.0f / (1.0f + expf(-(igv[0][i] + sr)));
            float z = 1.0f / (1.0f + expf(-(igv[1][i] + sz)));
            float n = tanhf(igv[2][i] + r * (sn + bnv));
            __stcg(&hnext[b * H_ + jg], n + z * (hval[i] - n));
        }

        // ---- per-b-group barrier (16 blocks share this h row range) --------
        __threadfence();
        __syncthreads();
        if (tid == 0) {
            atomicAdd(&g_bars[grp * 32], 1u);
            unsigned target = (unsigned)(t + 1) * 16u;
            volatile unsigned* p = &g_bars[grp * 32];
            while (*p < target) __nanosleep(32);
        }
        __syncthreads();
    }
}

// ======================= Kernel 3: final projection =========================
__global__ __launch_bounds__(128) void proj_kernel(
        const float* __restrict__ w_proj, const float* __restrict__ b_proj,
        float* __restrict__ out) {
    __shared__ float red[4];
    int b = blockIdx.x;
    float s = 0.f;
    for (int j = threadIdx.x; j < H_; j += 128)
        s += g_h2[0][b * H_ + j] * w_proj[j];   // T=512 even -> final h in buf 0
#pragma unroll
    for (int o = 16; o; o >>= 1) s += __shfl_down_sync(0xffffffffu, s, o);
    if ((threadIdx.x & 31) == 0) red[threadIdx.x >> 5] = s;
    __syncthreads();
    if (threadIdx.x == 0)
        out[b] = red[0] + red[1] + red[2] + red[3] + b_proj[0];
}

__global__ void zero_kernel() {
    int i = blockIdx.x * 256 + threadIdx.x;
    if (i < B_ * H_) g_h2[0][i] = 0.f;
    if (i < 8 * 32) g_bars[i] = 0u;   // reset group barriers every launch/replay
}

// ======================= launch ============================================
extern "C" void kernel_launch(void* const* d_in, const int* in_sizes, int n_in,
                              void* d_out, int out_size) {
    const float* x      = (const float*)d_in[0];  // (B,T,I)
    const float* w_ih   = (const float*)d_in[1];  // (3H,I)
    const float* w_hh   = (const float*)d_in[2];  // (3H,H)
    const float* b      = (const float*)d_in[3];  // (3H)
    const float* b_n    = (const float*)d_in[4];  // (H)
    const float* w_proj = (const float*)d_in[5];  // (1,H)
    const float* b_proj = (const float*)d_in[6];  // (1)
    float* out = (float*)d_out;                   // (B)

    cudaFuncSetAttribute(recur_kernel,
                         cudaFuncAttributeMaxDynamicSharedMemorySize,
                         SMEM_BYTES);

    igates_kernel<<<dim3(G3 / 64, (B_ * T_) / 64), 256>>>(x, w_ih, b);
    zero_kernel<<<(B_ * H_) / 256, 256>>>();
    recur_kernel<<<NBLK, 512, SMEM_BYTES>>>(w_hh, b_n);
    proj_kernel<<<B_, 128>>>(w_proj, b_proj, out);
}

// round 12
// speedup vs baseline: 1.4704x; 1.4124x over previous
#include <cuda_runtime.h>
#include <math.h>

#define B_  256
#define T_  512
#define I_  256
#define H_  512
#define G3  1536   // 3*H
#define NBLK 128

// ---------------- scratch (device globals: no allocation allowed) ----------
__device__ __align__(16) float g_igates[(size_t)T_ * B_ * G3]; // (t,b,g)
__device__ __align__(16) float g_h2[2][B_ * H_];               // double-buffered h
__device__ __align__(128) unsigned g_bars[8 * 32];             // 8 group ctrs, 128B apart

// ---------------- packed fp32x2 FMA (sm_100a+/103a) ------------------------
__device__ __forceinline__ unsigned long long ffma2(unsigned long long a,
                                                    unsigned long long b,
                                                    unsigned long long c) {
    unsigned long long d;
    asm("fma.rn.f32x2 %0, %1, %2, %3;" : "=l"(d) : "l"(a), "l"(b), "l"(c));
    return d;
}
__device__ __forceinline__ float pairsum(unsigned long long v) {
    float lo = __uint_as_float((unsigned int)(v & 0xffffffffull));
    float hi = __uint_as_float((unsigned int)(v >> 32));
    return lo + hi;
}
// igates kernel helper (70-float rows are 8B- but not 16B-aligned)
__device__ __forceinline__ void stage16(float* dst, const float* src) {
    float4 v = *(const float4*)src;
    *(float2*)(dst + 0) = make_float2(v.x, v.y);
    *(float2*)(dst + 2) = make_float2(v.z, v.w);
}

// ======================= Kernel 1: igates GEMM ==============================
__global__ __launch_bounds__(256) void igates_kernel(
        const float* __restrict__ x, const float* __restrict__ w_ih,
        const float* __restrict__ bias) {
    __shared__ __align__(16) float xs[64][70];
    __shared__ __align__(16) float ws[64][70];

    const int tid = threadIdx.x;
    const int tx = tid & 15;
    const int ty = tid >> 4;
    const int n0 = blockIdx.x * 64;
    const int m0 = blockIdx.y * 64;

    unsigned long long acc[4][4];
#pragma unroll
    for (int i = 0; i < 4; i++)
#pragma unroll
        for (int j = 0; j < 4; j++) acc[i][j] = 0ull;

    for (int kc = 0; kc < 4; kc++) {
        const int kb = kc * 64;
#pragma unroll
        for (int q = 0; q < 4; q++) {
            int qi = tid + 256 * q;
            int r = qi >> 4, kq = qi & 15;
            stage16(&xs[r][kq * 4], &x[(size_t)(m0 + r) * I_ + kb + kq * 4]);
            stage16(&ws[r][kq * 4], &w_ih[(size_t)(n0 + r) * I_ + kb + kq * 4]);
        }
        __syncthreads();
#pragma unroll 4
        for (int k2 = 0; k2 < 32; k2++) {
            unsigned long long xv[4], wv[4];
#pragma unroll
            for (int i = 0; i < 4; i++)
                xv[i] = *(const unsigned long long*)&xs[ty + 16 * i][2 * k2];
#pragma unroll
            for (int j = 0; j < 4; j++)
                wv[j] = *(const unsigned long long*)&ws[tx + 16 * j][2 * k2];
#pragma unroll
            for (int i = 0; i < 4; i++)
#pragma unroll
                for (int j = 0; j < 4; j++)
                    acc[i][j] = ffma2(xv[i], wv[j], acc[i][j]);
        }
        __syncthreads();
    }
#pragma unroll
    for (int i = 0; i < 4; i++) {
        int m = m0 + ty + 16 * i;
        int t = m & (T_ - 1);
        int bb = m >> 9;
        size_t base = ((size_t)t * B_ + bb) * G3;
#pragma unroll
        for (int j = 0; j < 4; j++) {
            int n = n0 + tx + 16 * j;
            g_igates[base + n] = pairsum(acc[i][j]) + bias[n];
        }
    }
}

// ============== Kernel 2: persistent GRU recurrence (512 steps) =============
// 128 blocks x 512 threads, 1 block/SM. Block tile 32b x 32j x 3g, K=512.
// Warp geometry engineered for the SM-wide 128B/cyc SMEM crossbar:
//   warp = (kz k-half, slot); lanes = 2b x 16j; thread = 4b x 1j x 3g.
//   hv: LDS.128 (2 rows + broadcast)  ~1 phase;  wv: LDS.128 bcast-ish ~2.
// w tile (96 x 512) stationary in SMEM for all 512 steps.
#define WS_STRIDE 516                 // 16B-aligned rows, 4-bank skew
#define HS_STRIDE 68                  // 16B-aligned rows, 4-bank skew
#define WS_FLOATS (96 * WS_STRIDE)    // 49536
#define HS_FLOATS (2 * 32 * HS_STRIDE)// 4352
#define SMEM_BYTES ((WS_FLOATS + HS_FLOATS) * 4)   // 215552 B

__global__ __launch_bounds__(512) void recur_kernel(
        const float* __restrict__ w_hh, const float* __restrict__ b_n) {
    extern __shared__ float smem[];
    float* ws = smem;                          // [96][WS_STRIDE]
    float* hs = smem + WS_FLOATS;              // [2][32][HS_STRIDE]
    float* red = hs;                           // reused after k-loop: [8][32][12]

    const int tid  = threadIdx.x;
    const int wid  = tid >> 5;
    const int lane = tid & 31;
    const int kz   = wid & 1;                  // k-half (chunk parity)
    const int slot = wid >> 1;                 // 0..7
    const int bg   = slot >> 1;                // 0..3  (8 b's each)
    const int jh   = slot & 1;                 // j-half
    const int lb   = lane & 1;
    const int lj   = lane >> 1;                // 0..15
    const int jj   = jh * 16 + lj;             // 0..31
    const int j0   = (blockIdx.x & 15) * 32;
    const int b0   = (blockIdx.x >> 4) * 32;
    const int grp  = blockIdx.x >> 4;
    const int jg   = j0 + jj;
    const int brow = bg * 8 + lb * 4;          // thread's first b-row (of 4)

    // ---- stationary w tile ------------------------------------------------
    for (int q = 0; q < 24; q++) {
        int qi = tid + 512 * q;                // [0, 12288) float4 ids
        int r = qi >> 7;                       // 0..95 = g*32 + jj
        int c4 = qi & 127;
        int grow = (r >> 5) * H_ + j0 + (r & 31);
        *(float4*)&ws[r * WS_STRIDE + c4 * 4] =
            *(const float4*)&w_hh[(size_t)grow * H_ + c4 * 4];
    }
    float bnv = b_n[jg];

    const int sr = tid >> 4;                   // staging row 0..31
    const int sc = tid & 15;                   // staging float4 col
    __syncthreads();

    for (int t = 0; t < T_; t++) {
        const float* __restrict__ hprev = g_h2[t & 1];
        float* __restrict__ hnext = g_h2[(t + 1) & 1];

        // ---- prefetch pointwise operands (kz==0 warps; warp-uniform pred) --
        float igv[4][3], hval[4];
        if (kz == 0) {
#pragma unroll
            for (int i = 0; i < 4; i++) {
                int b = b0 + brow + i;
                size_t ib = ((size_t)t * B_ + b) * G3;
#pragma unroll
                for (int g = 0; g < 3; g++)
                    igv[i][g] = __ldg(&g_igates[ib + g * H_ + jg]);
                hval[i] = __ldcg(&hprev[b * H_ + jg]);
            }
        }

        // ---- stage chunks 0 (buf0) and 1 (buf1) ----------------------------
        {
            float4 v0 = __ldcg((const float4*)&hprev[(size_t)(b0 + sr) * H_ + sc * 4]);
            float4 v1 = __ldcg((const float4*)&hprev[(size_t)(b0 + sr) * H_ + 64 + sc * 4]);
            *(float4*)&hs[(0 * 32 + sr) * HS_STRIDE + sc * 4] = v0;
            *(float4*)&hs[(1 * 32 + sr) * HS_STRIDE + sc * 4] = v1;
        }
        __syncthreads();

        unsigned long long acc[4][3];
#pragma unroll
        for (int i = 0; i < 4; i++)
#pragma unroll
            for (int g = 0; g < 3; g++) acc[i][g] = 0ull;

        const float* hsb = &hs[kz * 32 * HS_STRIDE];   // my parity buffer

        for (int cp = 0; cp < 4; cp++) {
            // prefetch next chunk pair (hidden behind compute)
            float4 p0, p1;
            if (cp < 3) {
                int kb2 = (2 * cp + 2) * 64;
                p0 = __ldcg((const float4*)&hprev[(size_t)(b0 + sr) * H_ + kb2 + sc * 4]);
                p1 = __ldcg((const float4*)&hprev[(size_t)(b0 + sr) * H_ + kb2 + 64 + sc * 4]);
            }
            const int kb = (2 * cp + kz) * 64;         // my chunk's global k base
#pragma unroll 4
            for (int q = 0; q < 16; q++) {             // 4 k-floats (2 pairs) each
                ulonglong2 wv0 = *(const ulonglong2*)&ws[(0 * 32 + jj) * WS_STRIDE + kb + 4 * q];
                ulonglong2 wv1 = *(const ulonglong2*)&ws[(1 * 32 + jj) * WS_STRIDE + kb + 4 * q];
                ulonglong2 wv2 = *(const ulonglong2*)&ws[(2 * 32 + jj) * WS_STRIDE + kb + 4 * q];
#pragma unroll
                for (int i = 0; i < 4; i++) {
                    ulonglong2 hv = *(const ulonglong2*)&hsb[(brow + i) * HS_STRIDE + 4 * q];
                    acc[i][0] = ffma2(hv.x, wv0.x, acc[i][0]);
                    acc[i][0] = ffma2(hv.y, wv0.y, acc[i][0]);
                    acc[i][1] = ffma2(hv.x, wv1.x, acc[i][1]);
                    acc[i][1] = ffma2(hv.y, wv1.y, acc[i][1]);
                    acc[i][2] = ffma2(hv.x, wv2.x, acc[i][2]);
                    acc[i][2] = ffma2(hv.y, wv2.y, acc[i][2]);
                }
            }
            __syncthreads();                   // all reads of this pair done
            if (cp < 3) {
                *(float4*)&hs[(0 * 32 + sr) * HS_STRIDE + sc * 4] = p0;
                *(float4*)&hs[(1 * 32 + sr) * HS_STRIDE + sc * 4] = p1;
            }
            __syncthreads();                   // new pair visible
        }

        // ---- k-split reduction via SMEM (reuses hs region) -----------------
        if (kz == 1) {
            float* mr = &red[(slot * 32 + lane) * 12];
#pragma unroll
            for (int i = 0; i < 4; i++)
#pragma unroll
                for (int g = 0; g < 3; g++)
                    mr[i * 3 + g] = pairsum(acc[i][g]);
        }
        __syncthreads();

        // ---- GRU pointwise (kz==0 warps) -----------------------------------
        if (kz == 0) {
            const float* orr = &red[(slot * 32 + lane) * 12];
#pragma unroll
            for (int i = 0; i < 4; i++) {
                float srg = pairsum(acc[i][0]) + orr[i * 3 + 0];
                float szg = pairsum(acc[i][1]) + orr[i * 3 + 1];
                float sng = pairsum(acc[i][2]) + orr[i * 3 + 2];
                float r = 1.0f / (1.0f + expf(-(igv[i][0] + srg)));
                float z = 1.0f / (1.0f + expf(-(igv[i][1] + szg)));
                float n = tanhf(igv[i][2] + r * (sng + bnv));
                int b = b0 + brow + i;
                __stcg(&hnext[b * H_ + jg], n + z * (hval[i] - n));
            }
        }

        // ---- per-b-group barrier (16 blocks share this h row range) --------
        __threadfence();
        __syncthreads();
        if (tid == 0) {
            atomicAdd(&g_bars[grp * 32], 1u);
            unsigned target = (unsigned)(t + 1) * 16u;
            volatile unsigned* p = &g_bars[grp * 32];
            while (*p < target) __nanosleep(32);
        }
        __syncthreads();
    }
}

// ======================= Kernel 3: final projection =========================
__global__ __launch_bounds__(128) void proj_kernel(
        const float* __restrict__ w_proj, const float* __restrict__ b_proj,
        float* __restrict__ out) {
    __shared__ float red[4];
    int b = blockIdx.x;
    float s = 0.f;
    for (int j = threadIdx.x; j < H_; j += 128)
        s += g_h2[0][b * H_ + j] * w_proj[j];   // T=512 even -> final h in buf 0
#pragma unroll
    for (int o = 16; o; o >>= 1) s += __shfl_down_sync(0xffffffffu, s, o);
    if ((threadIdx.x & 31) == 0) red[threadIdx.x >> 5] = s;
    __syncthreads();
    if (threadIdx.x == 0)
        out[b] = red[0] + red[1] + red[2] + red[3] + b_proj[0];
}

__global__ void zero_kernel() {
    int i = blockIdx.x * 256 + threadIdx.x;
    if (i < B_ * H_) g_h2[0][i] = 0.f;
    if (i < 8 * 32) g_bars[i] = 0u;   // reset group barriers every launch/replay
}

// ======================= launch ============================================
extern "C" void kernel_launch(void* const* d_in, const int* in_sizes, int n_in,
                              void* d_out, int out_size) {
    const float* x      = (const float*)d_in[0];  // (B,T,I)
    const float* w_ih   = (const float*)d_in[1];  // (3H,I)
    const float* w_hh   = (const float*)d_in[2];  // (3H,H)
    const float* b      = (const float*)d_in[3];  // (3H)
    const float* b_n    = (const float*)d_in[4];  // (H)
    const float* w_proj = (const float*)d_in[5];  // (1,H)
    const float* b_proj = (const float*)d_in[6];  // (1)
    float* out = (float*)d_out;                   // (B)

    cudaFuncSetAttribute(recur_kernel,
                         cudaFuncAttributeMaxDynamicSharedMemorySize,
                         SMEM_BYTES);

    igates_kernel<<<dim3(G3 / 64, (B_ * T_) / 64), 256>>>(x, w_ih, b);
    zero_kernel<<<(B_ * H_) / 256, 256>>>();
    recur_kernel<<<NBLK, 512, SMEM_BYTES>>>(w_hh, b_n);
    proj_kernel<<<B_, 128>>>(w_proj, b_proj, out);
}

// round 14
// speedup vs baseline: 1.8656x; 1.2688x over previous
#include <cuda_runtime.h>
#include <cuda_bf16.h>
#include <mma.h>
#include <math.h>
#include <stdint.h>

using namespace nvcuda;

#define B_  256
#define T_  512
#define I_  256
#define H_  512
#define G3  1536   // 3*H
#define NBLK 128

// ---------------- scratch (device globals: no allocation allowed) ----------
__device__ __align__(16) float g_igates[(size_t)T_ * B_ * G3]; // (t,b,g)
__device__ __align__(16) float g_h2[2][B_ * H_];               // double-buffered h
__device__ __align__(128) unsigned g_bars[8 * 32];             // 8 group ctrs
// w_hh bf16 splits: [split][16 j-tiles][96 rows][512 k]
__device__ __align__(16) __nv_bfloat16 g_wsplit[2][16][96 * 512];

// ---------------- helpers ---------------------------------------------------
__device__ __forceinline__ unsigned long long ffma2(unsigned long long a,
                                                    unsigned long long b,
                                                    unsigned long long c) {
    unsigned long long d;
    asm("fma.rn.f32x2 %0, %1, %2, %3;" : "=l"(d) : "l"(a), "l"(b), "l"(c));
    return d;
}
__device__ __forceinline__ float pairsum(unsigned long long v) {
    float lo = __uint_as_float((unsigned int)(v & 0xffffffffull));
    float hi = __uint_as_float((unsigned int)(v >> 32));
    return lo + hi;
}
__device__ __forceinline__ void stage16(float* dst, const float* src) {
    float4 v = *(const float4*)src;
    *(float2*)(dst + 0) = make_float2(v.x, v.y);
    *(float2*)(dst + 2) = make_float2(v.z, v.w);
}
__device__ __forceinline__ unsigned pbf2(float a, float b) {
    __nv_bfloat162 t = __floats2bfloat162_rn(a, b);
    return *reinterpret_cast<unsigned*>(&t);
}
__device__ __forceinline__ float bhi(float x) {
    return __bfloat162float(__float2bfloat16(x));
}

// ======================= Kernel 0: split w_hh -> bf16 hi/lo =================
// Per j-tile jt: row r (0..95) = gate (r>>5), j = jt*32 + (r&31). Linear k.
__global__ __launch_bounds__(256) void prep_w_kernel(const float* __restrict__ w_hh) {
    int id = blockIdx.x * 256 + threadIdx.x;    // 98304 total, 8 k-elems each
    int jt = id / 6144;
    int rem = id % 6144;
    int r = rem >> 6;
    int kg = (rem & 63) * 8;
    int row = (r >> 5) * H_ + jt * 32 + (r & 31);

    float4 f0 = *(const float4*)&w_hh[(size_t)row * H_ + kg];
    float4 f1 = *(const float4*)&w_hh[(size_t)row * H_ + kg + 4];
    float x[8] = {f0.x, f0.y, f0.z, f0.w, f1.x, f1.y, f1.z, f1.w};

    uint4 hv, lv;
    unsigned* hp = (unsigned*)&hv;
    unsigned* lp = (unsigned*)&lv;
#pragma unroll
    for (int i = 0; i < 4; i++) {
        float a = x[2 * i], b = x[2 * i + 1];
        hp[i] = pbf2(bhi(a), bhi(b));
        lp[i] = pbf2(a - bhi(a), b - bhi(b));
    }
    *(uint4*)&g_wsplit[0][jt][r * 512 + kg] = hv;
    *(uint4*)&g_wsplit[1][jt][r * 512 + kg] = lv;
}

// ======================= Kernel 1: igates GEMM (FFMA2, proven) ==============
__global__ __launch_bounds__(256) void igates_kernel(
        const float* __restrict__ x, const float* __restrict__ w_ih,
        const float* __restrict__ bias) {
    __shared__ __align__(16) float xs[64][70];
    __shared__ __align__(16) float ws[64][70];

    const int tid = threadIdx.x;
    const int tx = tid & 15;
    const int ty = tid >> 4;
    const int n0 = blockIdx.x * 64;
    const int m0 = blockIdx.y * 64;

    unsigned long long acc[4][4];
#pragma unroll
    for (int i = 0; i < 4; i++)
#pragma unroll
        for (int j = 0; j < 4; j++) acc[i][j] = 0ull;

    for (int kc = 0; kc < 4; kc++) {
        const int kb = kc * 64;
#pragma unroll
        for (int q = 0; q < 4; q++) {
            int qi = tid + 256 * q;
            int r = qi >> 4, kq = qi & 15;
            stage16(&xs[r][kq * 4], &x[(size_t)(m0 + r) * I_ + kb + kq * 4]);
            stage16(&ws[r][kq * 4], &w_ih[(size_t)(n0 + r) * I_ + kb + kq * 4]);
        }
        __syncthreads();
#pragma unroll 4
        for (int k2 = 0; k2 < 32; k2++) {
            unsigned long long xv[4], wv[4];
#pragma unroll
            for (int i = 0; i < 4; i++)
                xv[i] = *(const unsigned long long*)&xs[ty + 16 * i][2 * k2];
#pragma unroll
            for (int j = 0; j < 4; j++)
                wv[j] = *(const unsigned long long*)&ws[tx + 16 * j][2 * k2];
#pragma unroll
            for (int i = 0; i < 4; i++)
#pragma unroll
                for (int j = 0; j < 4; j++)
                    acc[i][j] = ffma2(xv[i], wv[j], acc[i][j]);
        }
        __syncthreads();
    }
#pragma unroll
    for (int i = 0; i < 4; i++) {
        int m = m0 + ty + 16 * i;
        int t = m & (T_ - 1);
        int bb = m >> 9;
        size_t base = ((size_t)t * B_ + bb) * G3;
#pragma unroll
        for (int j = 0; j < 4; j++) {
            int n = n0 + tx + 16 * j;
            g_igates[base + n] = pairsum(acc[i][j]) + bias[n];
        }
    }
}

// ============== Kernel 2: persistent wmma bf16-split GRU recurrence =========
// 128 blocks x 512 thr, 1/SM. Per step per block:
//   D[96 = 3g x 32j, 32 b] = W[96,512] @ H[32,512]^T
// bf16 2-split (hh + hl + lh) accumulated in ONE f32 wmma accumulator.
// 12 warps each own an m16 x n16 D tile. w splits SMEM-stationary.
#define WS_LD 520                  // bf16 elems; 1040B row ≡ 16 mod 128 -> ldsm OK
#define HS_LD 72                   // 144B row ≡ 16 mod 128
#define RED_LD 36                  // f32; 144B row
#define WS_BYTES (96 * WS_LD * 2)  // 99,840 per split
#define HS_ELEMS (32 * HS_LD)      // 2304 per (buf, split)
#define SM_WHI 0
#define SM_WLO WS_BYTES
#define SM_HS  (2 * WS_BYTES)      // 199,680; 2 bufs x 2 splits x 4608B
#define SMEM_R (SM_HS + 4 * HS_ELEMS * 2)   // 218,112 B

__global__ __launch_bounds__(512) void recur_kernel(const float* __restrict__ b_n) {
    extern __shared__ uint8_t sm[];
    __nv_bfloat16* wshi = (__nv_bfloat16*)(sm + SM_WHI);
    __nv_bfloat16* wslo = (__nv_bfloat16*)(sm + SM_WLO);
    __nv_bfloat16* hsb  = (__nv_bfloat16*)(sm + SM_HS);  // [buf][split][32][HS_LD]
    float* red = (float*)(sm + SM_HS);                   // epilogue reuse

    const int tid = threadIdx.x;
    const int wid = tid >> 5;
    const int jt = blockIdx.x & 15;
    const int j0 = jt * 32;
    const int b0 = (blockIdx.x >> 4) * 32;
    const int grp = blockIdx.x >> 4;
    const int mt = wid >> 1;       // 0..5 (m-tile), valid for wid < 12
    const int nh = wid & 1;        // 0..1 (n-half)

    // ---- one-time copy of both w splits into SMEM --------------------------
    {
        const __nv_bfloat16* ghi = g_wsplit[0][jt];
        const __nv_bfloat16* glo = g_wsplit[1][jt];
        for (int q = 0; q < 12; q++) {          // 6144 uint4 per split
            int i = tid + 512 * q;
            int r = i >> 6, c = i & 63;
            *(uint4*)&wshi[r * WS_LD + c * 8] = *(const uint4*)&ghi[r * 512 + c * 8];
            *(uint4*)&wslo[r * WS_LD + c * 8] = *(const uint4*)&glo[r * 512 + c * 8];
        }
    }
    const int pj = tid & 31;
    const int pb = tid >> 5;                    // batches pb, pb+16
    const float bnv = b_n[j0 + pj];
    const int sr = tid >> 4;                    // staging row 0..31
    const int sc = tid & 15;                    // staging k-quad
    __syncthreads();

    for (int t = 0; t < T_; t++) {
        const float* __restrict__ hprev = g_h2[t & 1];
        float* __restrict__ hnext = g_h2[(t + 1) & 1];

        // ---- prefetch pointwise operands -----------------------------------
        float igv[2][3], hval[2];
#pragma unroll
        for (int half = 0; half < 2; half++) {
            int b = b0 + pb + 16 * half;
            size_t ib = ((size_t)t * B_ + b) * G3;
#pragma unroll
            for (int g = 0; g < 3; g++)
                igv[half][g] = __ldg(&g_igates[ib + g * H_ + j0 + pj]);
            hval[half] = __ldcg(&hprev[b * H_ + j0 + pj]);
        }

        // ---- stage h chunk 0 (hi/lo bf16) into buf 0 -----------------------
        {
            float4 v = __ldcg((const float4*)&hprev[(size_t)(b0 + sr) * H_ + sc * 4]);
            __nv_bfloat16* dhi = hsb;
            __nv_bfloat16* dlo = hsb + HS_ELEMS;
            *(unsigned*)&dhi[sr * HS_LD + sc * 4]     = pbf2(bhi(v.x), bhi(v.y));
            *(unsigned*)&dhi[sr * HS_LD + sc * 4 + 2] = pbf2(bhi(v.z), bhi(v.w));
            *(unsigned*)&dlo[sr * HS_LD + sc * 4]     = pbf2(v.x - bhi(v.x), v.y - bhi(v.y));
            *(unsigned*)&dlo[sr * HS_LD + sc * 4 + 2] = pbf2(v.z - bhi(v.z), v.w - bhi(v.w));
        }
        __syncthreads();

        wmma::fragment<wmma::accumulator, 16, 16, 16, float> acc;
        wmma::fill_fragment(acc, 0.0f);

        for (int cp = 0; cp < 8; cp++) {        // K = 8 chunks of 64
            float4 pf;
            if (cp < 7)
                pf = __ldcg((const float4*)
                        &hprev[(size_t)(b0 + sr) * H_ + (cp + 1) * 64 + sc * 4]);

            if (wid < 12) {
                const __nv_bfloat16* bhiP = hsb + (cp & 1) * 2 * HS_ELEMS;
                const __nv_bfloat16* bloP = bhiP + HS_ELEMS;
#pragma unroll
                for (int ks = 0; ks < 4; ks++) {
                    int kg = cp * 64 + ks * 16;
                    wmma::fragment<wmma::matrix_a, 16, 16, 16, __nv_bfloat16,
                                   wmma::row_major> ahi, alo;
                    wmma::fragment<wmma::matrix_b, 16, 16, 16, __nv_bfloat16,
                                   wmma::col_major> bhiF, bloF;
                    wmma::load_matrix_sync(ahi, &wshi[mt * 16 * WS_LD + kg], WS_LD);
                    wmma::load_matrix_sync(alo, &wslo[mt * 16 * WS_LD + kg], WS_LD);
                    wmma::load_matrix_sync(bhiF, &bhiP[nh * 16 * HS_LD + ks * 16], HS_LD);
                    wmma::load_matrix_sync(bloF, &bloP[nh * 16 * HS_LD + ks * 16], HS_LD);
                    wmma::mma_sync(acc, ahi, bhiF, acc);   // hi*hi
                    wmma::mma_sync(acc, ahi, bloF, acc);   // hi*lo
                    wmma::mma_sync(acc, alo, bhiF, acc);   // lo*hi
                }
            }
            if (cp < 7) {
                __nv_bfloat16* dhi = hsb + ((cp + 1) & 1) * 2 * HS_ELEMS;
                __nv_bfloat16* dlo = dhi + HS_ELEMS;
                *(unsigned*)&dhi[sr * HS_LD + sc * 4]     = pbf2(bhi(pf.x), bhi(pf.y));
                *(unsigned*)&dhi[sr * HS_LD + sc * 4 + 2] = pbf2(bhi(pf.z), bhi(pf.w));
                *(unsigned*)&dlo[sr * HS_LD + sc * 4]     = pbf2(pf.x - bhi(pf.x), pf.y - bhi(pf.y));
                *(unsigned*)&dlo[sr * HS_LD + sc * 4 + 2] = pbf2(pf.z - bhi(pf.z), pf.w - bhi(pf.w));
            }
            __syncthreads();
        }

        // ---- epilogue: acc -> SMEM (row = g*32+jj, col = batch) ------------
        if (wid < 12)
            wmma::store_matrix_sync(&red[(mt * 16) * RED_LD + nh * 16], acc,
                                    RED_LD, wmma::mem_row_major);
        __syncthreads();

        // ---- GRU pointwise --------------------------------------------------
#pragma unroll
        for (int half = 0; half < 2; half++) {
            int bb = pb + 16 * half;
            float sr_ = red[(0 * 32 + pj) * RED_LD + bb];
            float sz_ = red[(1 * 32 + pj) * RED_LD + bb];
            float sn_ = red[(2 * 32 + pj) * RED_LD + bb];
            float r = 1.0f / (1.0f + expf(-(igv[half][0] + sr_)));
            float z = 1.0f / (1.0f + expf(-(igv[half][1] + sz_)));
            float n = tanhf(igv[half][2] + r * (sn_ + bnv));
            __stcg(&hnext[(b0 + bb) * H_ + j0 + pj], n + z * (hval[half] - n));
        }

        // ---- per-b-group barrier (16 blocks share these h rows) ------------
        __threadfence();
        __syncthreads();
        if (tid == 0) {
            atomicAdd(&g_bars[grp * 32], 1u);
            unsigned target = (unsigned)(t + 1) * 16u;
            volatile unsigned* p = &g_bars[grp * 32];
            while (*p < target) __nanosleep(32);
        }
        __syncthreads();
    }
}

// ======================= Kernel 3: final projection =========================
__global__ __launch_bounds__(128) void proj_kernel(
        const float* __restrict__ w_proj, const float* __restrict__ b_proj,
        float* __restrict__ out) {
    __shared__ float red[4];
    int b = blockIdx.x;
    float s = 0.f;
    for (int j = threadIdx.x; j < H_; j += 128)
        s += g_h2[0][b * H_ + j] * w_proj[j];   // T even -> final h in buf 0
#pragma unroll
    for (int o = 16; o; o >>= 1) s += __shfl_down_sync(0xffffffffu, s, o);
    if ((threadIdx.x & 31) == 0) red[threadIdx.x >> 5] = s;
    __syncthreads();
    if (threadIdx.x == 0)
        out[b] = red[0] + red[1] + red[2] + red[3] + b_proj[0];
}

__global__ void zero_kernel() {
    int i = blockIdx.x * 256 + threadIdx.x;
    if (i < B_ * H_) g_h2[0][i] = 0.f;
    if (i < 8 * 32) g_bars[i] = 0u;
}

// ======================= launch ============================================
extern "C" void kernel_launch(void* const* d_in, const int* in_sizes, int n_in,
                              void* d_out, int out_size) {
    const float* x      = (const float*)d_in[0];  // (B,T,I)
    const float* w_ih   = (const float*)d_in[1];  // (3H,I)
    const float* w_hh   = (const float*)d_in[2];  // (3H,H)
    const float* b      = (const float*)d_in[3];  // (3H)
    const float* b_n    = (const float*)d_in[4];  // (H)
    const float* w_proj = (const float*)d_in[5];  // (1,H)
    const float* b_proj = (const float*)d_in[6];  // (1)
    float* out = (float*)d_out;                   // (B)

    cudaFuncSetAttribute(recur_kernel,
                         cudaFuncAttributeMaxDynamicSharedMemorySize, SMEM_R);

    prep_w_kernel<<<384, 256>>>(w_hh);
    igates_kernel<<<dim3(G3 / 64, (B_ * T_) / 64), 256>>>(x, w_ih, b);
    zero_kernel<<<(B_ * H_) / 256, 256>>>();
    recur_kernel<<<NBLK, 512, SMEM_R>>>(b_n);
    proj_kernel<<<B_, 128>>>(w_proj, b_proj, out);
}